// round 5
// baseline (speedup 1.0000x reference)
#include <cuda_runtime.h>
#include <cuda_bf16.h>
#include <math.h>

// Problem constants (static per the reference module)
#define BB      4
#define NPER    2000
#define NATOMS  (BB*NPER)
#define NN      11            // n = 0..10 per axis
#define NT      128           // threads per k_main block

#define KSQ_MAX_F   9.8696044010893586f   // fp32(pi^2), as JAX compares
#define TWOPI_F     6.2831854820251465f
#define INV_SELF    0.0634936359342410f   // 1/(sigma*(2*pi)^1.5)
#define NORM_F      90.0474f
#define EPS_F       1e-6f

typedef unsigned long long u64;

__device__ __forceinline__ u64 pk(float lo, float hi) {
    u64 r; asm("mov.b64 %0, {%1, %2};" : "=l"(r) : "f"(lo), "f"(hi)); return r;
}
__device__ __forceinline__ float2 upk(u64 v) {
    float lo, hi; asm("mov.b64 {%0, %1}, %2;" : "=f"(lo), "=f"(hi) : "l"(v));
    return make_float2(lo, hi);
}
__device__ __forceinline__ void fma2(u64& d, u64 a, u64 b) {
    asm("fma.rn.f32x2 %0, %1, %2, %0;" : "+l"(d) : "l"(a), "l"(b));
}
__device__ __forceinline__ u64 add2(u64 a, u64 b) {
    u64 d; asm("add.rn.f32x2 %0, %1, %2;" : "=l"(d) : "l"(a), "l"(b)); return d;
}

// ---------------- device scratch ----------------
__device__ float    g_cinv[BB][3][3];
__device__ float    g_vol[BB];
__device__ float    g_pot[BB];
__device__ float2   g_tabx[BB][NN][NPER];      // q * e^{i 2pi n s0}
__device__ float2   g_taby[BB][NN][NPER];      //     e^{i 2pi n s1}
// z table in bf16x2 (low = cos, high = sin), n = 1..10 -> [n-1]; row = 40 B
__device__ unsigned g_tabz[BB][NPER][10];

// ---------------- kernel 1: phase tables, thread = (axis, n, atom) ------------
__global__ void k_tab(const float* __restrict__ q, const float* __restrict__ r,
                      const float* __restrict__ cell) {
    int idx = blockIdx.x * blockDim.x + threadIdx.x;
    if (idx >= 3 * NN * NATOMS) return;
    int axis = idx / (NN * NATOMS);
    int rem  = idx - axis * (NN * NATOMS);
    int n    = rem / NATOMS;
    int ga   = rem - n * NATOMS;
    int b    = ga / NPER;
    int a    = ga - b * NPER;

    const float* m = cell + b * 9;
    float m00=m[0], m01=m[1], m02=m[2];
    float m10=m[3], m11=m[4], m12=m[5];
    float m20=m[6], m21=m[7], m22=m[8];
    float c00 = m11*m22 - m12*m21;
    float c01 = m12*m20 - m10*m22;
    float c02 = m10*m21 - m11*m20;
    float det = m00*c00 + m01*c01 + m02*c02;
    float inv = 1.0f / det;
    float i00 = c00 * inv;
    float i01 = (m02*m21 - m01*m22) * inv;
    float i02 = (m01*m12 - m02*m11) * inv;
    float i10 = c01 * inv;
    float i11 = (m00*m22 - m02*m20) * inv;
    float i12 = (m02*m10 - m00*m12) * inv;
    float i20 = c02 * inv;
    float i21 = (m01*m20 - m00*m21) * inv;
    float i22 = (m00*m11 - m01*m10) * inv;

    if (axis == 0 && n == 0 && a == 0) {
        g_cinv[b][0][0]=i00; g_cinv[b][0][1]=i01; g_cinv[b][0][2]=i02;
        g_cinv[b][1][0]=i10; g_cinv[b][1][1]=i11; g_cinv[b][1][2]=i12;
        g_cinv[b][2][0]=i20; g_cinv[b][2][1]=i21; g_cinv[b][2][2]=i22;
        g_vol[b] = det;
        g_pot[b] = 0.0f;
    }

    float r0 = r[3*ga+0], r1 = r[3*ga+1], r2 = r[3*ga+2];
    float s;
    if (axis == 0)      s = r0*i00 + r1*i10 + r2*i20;
    else if (axis == 1) s = r0*i01 + r1*i11 + r2*i21;
    else                s = r0*i02 + r1*i12 + r2*i22;

    float u = (float)n * s;
    float f = u - rintf(u);
    float si, co;
    sincospif(2.0f * f, &si, &co);

    if (axis == 0) {
        float qv = q[ga];
        g_tabx[b][n][a] = make_float2(qv * co, qv * si);
    } else if (axis == 1) {
        g_taby[b][n][a] = make_float2(co, si);
    } else if (n >= 1) {
        unsigned p;   // high = bf16(sin), low = bf16(cos)
        asm("cvt.rn.bf16x2.f32 %0, %1, %2;" : "=r"(p) : "f"(si), "f"(co));
        g_tabz[b][a][n-1] = p;
    }
}

// ---------------- kernel 2: structure factors (f32x2) + fused reduction -------
// Block = (b, n1, m2). Both n2 signs and all n3 handled per block.
__global__ void __launch_bounds__(NT) k_main() {
    int blk = blockIdx.x;
    int b   = blk / 121;
    int rem = blk - b * 121;
    int n1  = rem / 11;
    int m2  = rem - n1 * 11;

    float g00 = TWOPI_F*g_cinv[b][0][0], g01 = TWOPI_F*g_cinv[b][1][0], g02 = TWOPI_F*g_cinv[b][2][0];
    float g10 = TWOPI_F*g_cinv[b][0][1], g11 = TWOPI_F*g_cinv[b][1][1], g12 = TWOPI_F*g_cinv[b][2][1];
    float g20 = TWOPI_F*g_cinv[b][0][2], g21 = TWOPI_F*g_cinv[b][1][2], g22 = TWOPI_F*g_cinv[b][2][2];

    // conservative block activity filter
    bool any = false;
    #pragma unroll
    for (int sg = 0; sg < 2; sg++) {
        float fn2 = sg ? -(float)m2 : (float)m2;
        #pragma unroll
        for (int t = 0; t < 21; t++) {
            float n3 = (float)(t - 10);
            float kv0 = n1*g00 + fn2*g01 + n3*g02;
            float kv1 = n1*g10 + fn2*g11 + n3*g12;
            float kv2 = n1*g20 + fn2*g21 + n3*g22;
            float ksq = kv0*kv0 + kv1*kv1 + kv2*kv2;
            any = any || (ksq > 0.0f && ksq <= KSQ_MAX_F * 1.001f);
        }
    }
    if (!any) return;

    const float2* __restrict__ tx = &g_tabx[b][n1][0];
    const float2* __restrict__ ty = &g_taby[b][m2][0];

    float cr0 = 0.f, ci0 = 0.f, cr1 = 0.f, ci1 = 0.f;
    u64 P0[10], M0[10], P1[10], M1[10];   // M stored as (re, -im)
    #pragma unroll
    for (int m = 0; m < 10; m++) { P0[m]=0; M0[m]=0; P1[m]=0; M1[m]=0; }

    for (int a = threadIdx.x; a < NPER; a += NT) {
        float2 X = tx[a];
        float2 Y = ty[a];
        float p  = X.x*Y.x, qq = X.y*Y.y, rr = X.x*Y.y, ss = X.y*Y.x;
        float ar0 = p - qq, ar1 = p + qq;       // n2 = +m2 / -m2
        float ai0 = rr + ss, ai1 = ss - rr;
        cr0 += ar0; ci0 += ai0; cr1 += ar1; ci1 += ai1;
        u64 A0 = pk(ar0, ar0), I0 = pk(ai0, ai0), nI0 = pk(-ai0, -ai0);
        u64 A1 = pk(ar1, ar1), I1 = pk(ai1, ai1), nI1 = pk(-ai1, -ai1);

        const uint2* zp = (const uint2*)&g_tabz[b][a][0];
        uint2 zw0 = zp[0], zw1 = zp[1], zw2 = zp[2], zw3 = zp[3], zw4 = zp[4];
        unsigned zu[10] = {zw0.x, zw0.y, zw1.x, zw1.y, zw2.x,
                           zw2.y, zw3.x, zw3.y, zw4.x, zw4.y};
        #pragma unroll
        for (int m = 0; m < 10; m++) {
            unsigned u = zu[m];
            float Zx  = __uint_as_float(u << 16);
            unsigned hy = u & 0xffff0000u;
            float Zy  = __uint_as_float(hy);
            float nZy = __uint_as_float(hy ^ 0x80000000u);
            u64 w1 = pk(Zx, Zy);     // ( Zx,  Zy)
            u64 w2 = pk(nZy, Zx);    // (-Zy,  Zx)
            // P(+n3): (re,im) += ar*w1 + ai*w2
            fma2(P0[m], A0, w1); fma2(P0[m], I0, w2);
            fma2(P1[m], A1, w1); fma2(P1[m], I1, w2);
            // M(-n3) stored (re,-im): += ar*w1 + (-ai)*w2
            fma2(M0[m], A0, w1); fma2(M0[m], nI0, w2);
            fma2(M1[m], A1, w1); fma2(M1[m], nI1, w2);
        }
    }

    // ---- pack to 42 complex entries, 3-level warp reduce -> 16 partials ----
    __shared__ float red[16][84];
    __shared__ float cont[NT];
    u64 packed[42];
    packed[0] = pk(cr0, ci0);
    packed[1] = pk(cr1, ci1);
    #pragma unroll
    for (int m = 0; m < 10; m++) {
        packed[2 + m]  = P0[m];
        packed[12 + m] = M0[m];
        packed[22 + m] = P1[m];
        packed[32 + m] = M1[m];
    }
    int w = threadIdx.x >> 5, lane = threadIdx.x & 31;
    #pragma unroll
    for (int j = 0; j < 42; j++) {
        u64 v = packed[j];
        v = add2(v, __shfl_xor_sync(0xffffffffu, v, 16));
        v = add2(v, __shfl_xor_sync(0xffffffffu, v, 8));
        v = add2(v, __shfl_xor_sync(0xffffffffu, v, 4));
        if (lane < 4) {
            float2 f2 = upk(v);
            red[w*4 + lane][2*j]   = f2.x;
            red[w*4 + lane][2*j+1] = f2.y;
        }
    }
    __syncthreads();

    // ---- per-kpoint weighting ----
    float c = 0.0f;
    int t = threadIdx.x;
    if (t < 42) {
        int sgn = t / 21, j = t - sgn * 21;      // j = n3 index 0..20
        if (!(m2 == 0 && sgn == 1)) {            // n2 = -0 duplicates +0
            int o;
            if (j == 10)      o = sgn;                       // center
            else if (j > 10)  o = 2  + sgn*20 + (j - 11);    // P bank, m = j-10
            else              o = 12 + sgn*20 + (9 - j);     // M bank, m = 10-j
            float Sr = 0.0f, Sv = 0.0f;
            #pragma unroll
            for (int pI = 0; pI < 16; pI++) {
                Sr += red[pI][2*o];
                Sv += red[pI][2*o+1];
            }
            float Si = (j < 10) ? -Sv : Sv;      // M bank stored (re,-im)
            float fn2 = sgn ? -(float)m2 : (float)m2;
            float n3  = (float)(j - 10);
            float kv0 = n1*g00 + fn2*g01 + n3*g02;
            float kv1 = n1*g10 + fn2*g11 + n3*g12;
            float kv2 = n1*g20 + fn2*g21 + n3*g22;
            float ksq = kv0*kv0 + kv1*kv1 + kv2*kv2;
            if (ksq > 0.0f && ksq <= KSQ_MAX_F) {
                float wgt  = (n1 > 0) ? 2.0f : 1.0f;
                float kfac = expf(-0.5f * ksq) / (ksq + EPS_F);
                c = wgt * kfac * (Sr*Sr + Si*Si);
            }
        }
    }
    cont[t] = c;
    __syncthreads();
    #pragma unroll
    for (int s = NT/2; s > 0; s >>= 1) {
        if (t < s) cont[t] += cont[t + s];
        __syncthreads();
    }
    if (t == 0) atomicAdd(&g_pot[b], cont[0]);
}

// ---------------- kernel 3: self energy + final output ----------------
__global__ void k_final(const float* __restrict__ q, float* __restrict__ out) {
    int b = blockIdx.x;
    __shared__ float sd[128];
    float s = 0.0f;
    for (int a = threadIdx.x; a < NPER; a += 128) {
        float qv = q[b * NPER + a];
        s += qv * qv;
    }
    sd[threadIdx.x] = s;
    __syncthreads();
    #pragma unroll
    for (int t = 64; t > 0; t >>= 1) {
        if (threadIdx.x < t) sd[threadIdx.x] += sd[threadIdx.x + t];
        __syncthreads();
    }
    if (threadIdx.x == 0) {
        float pot = g_pot[b] / g_vol[b] - sd[0] * INV_SELF;
        out[b] = pot * NORM_F;
    }
}

// ---------------- launch ----------------
extern "C" void kernel_launch(void* const* d_in, const int* in_sizes, int n_in,
                              void* d_out, int out_size) {
    const float* q    = (const float*)d_in[0];
    const float* r    = (const float*)d_in[1];
    const float* cell = (const float*)d_in[2];
    float* out = (float*)d_out;

    k_tab<<<(3 * NN * NATOMS + 255) / 256, 256>>>(q, r, cell);
    k_main<<<BB * 121, NT>>>();
    k_final<<<BB, 128>>>(q, out);
}

// round 6
// speedup vs baseline: 1.0864x; 1.0864x over previous
#include <cuda_runtime.h>
#include <math.h>

// Problem constants (static per the reference module)
#define BB      4
#define NPER    2000
#define NATOMS  (BB*NPER)
#define NN      11            // n = 0..10 per axis
#define NT      128           // threads per k_main block

#define KSQ_MAX_F   9.8696044010893586f   // fp32(pi^2), as JAX compares
#define TWOPI_F     6.2831854820251465f
#define INV_SELF    0.0634936359342410f   // 1/(sigma*(2*pi)^1.5)
#define NORM_F      90.0474f
#define EPS_F       1e-6f

typedef unsigned long long u64;

__device__ __forceinline__ u64 pk(float lo, float hi) {
    u64 r; asm("mov.b64 %0, {%1, %2};" : "=l"(r) : "f"(lo), "f"(hi)); return r;
}
__device__ __forceinline__ float2 upk(u64 v) {
    float lo, hi; asm("mov.b64 {%0, %1}, %2;" : "=f"(lo), "=f"(hi) : "l"(v));
    return make_float2(lo, hi);
}
__device__ __forceinline__ void fma2(u64& d, u64 a, u64 b) {
    asm("fma.rn.f32x2 %0, %1, %2, %0;" : "+l"(d) : "l"(a), "l"(b));
}
__device__ __forceinline__ u64 add2(u64 a, u64 b) {
    u64 d; asm("add.rn.f32x2 %0, %1, %2;" : "=l"(d) : "l"(a), "l"(b)); return d;
}

// fast sinpi/cospi on f in [-0.5, 0.5] (Taylor, max err ~3.6e-6 abs)
__device__ __forceinline__ void sincospi_fast(float f, float* s, float* c) {
    float t = f * f;
    float sp = fmaf(t, 0.0821458866f, -0.599264529f);
    sp = fmaf(t, sp, 2.55016404f);
    sp = fmaf(t, sp, -5.16771278f);
    sp = fmaf(t, sp, 3.14159265f);
    *s = f * sp;
    float cp = fmaf(t, -0.0258068917f, 0.235330631f);
    cp = fmaf(t, cp, -1.33526277f);
    cp = fmaf(t, cp, 4.05871213f);
    cp = fmaf(t, cp, -4.93480220f);
    *c = fmaf(t, cp, 1.0f);
}

// ---------------- device scratch ----------------
__device__ float  g_cinv[BB][3][3];
__device__ float  g_vol[BB];
__device__ float  g_pot[BB];
__device__ float2 g_tabx[BB][NN][NPER];   // q * e^{i 2pi n s0}
__device__ float2 g_taby[BB][NN][NPER];   //     e^{i 2pi n s1}
__device__ float2 g_tabz[BB][10][NPER];   //     e^{i 2pi m s2}, m = 1..10 -> [m-1]

// ---------------- kernel 1: phase tables, thread = (n, atom) ----------------
__global__ void k_tab(const float* __restrict__ q, const float* __restrict__ r,
                      const float* __restrict__ cell) {
    int idx = blockIdx.x * blockDim.x + threadIdx.x;
    if (idx >= NN * NATOMS) return;
    int n  = idx / NATOMS;
    int ga = idx - n * NATOMS;
    int b  = ga / NPER;
    int a  = ga - b * NPER;

    const float* m = cell + b * 9;
    float m00=m[0], m01=m[1], m02=m[2];
    float m10=m[3], m11=m[4], m12=m[5];
    float m20=m[6], m21=m[7], m22=m[8];
    float c00 = m11*m22 - m12*m21;
    float c01 = m12*m20 - m10*m22;
    float c02 = m10*m21 - m11*m20;
    float det = m00*c00 + m01*c01 + m02*c02;
    float inv = 1.0f / det;
    float i00 = c00 * inv;
    float i01 = (m02*m21 - m01*m22) * inv;
    float i02 = (m01*m12 - m02*m11) * inv;
    float i10 = c01 * inv;
    float i11 = (m00*m22 - m02*m20) * inv;
    float i12 = (m02*m10 - m00*m12) * inv;
    float i20 = c02 * inv;
    float i21 = (m01*m20 - m00*m21) * inv;
    float i22 = (m00*m11 - m01*m10) * inv;

    if (n == 0 && a == 0) {
        g_cinv[b][0][0]=i00; g_cinv[b][0][1]=i01; g_cinv[b][0][2]=i02;
        g_cinv[b][1][0]=i10; g_cinv[b][1][1]=i11; g_cinv[b][1][2]=i12;
        g_cinv[b][2][0]=i20; g_cinv[b][2][1]=i21; g_cinv[b][2][2]=i22;
        g_vol[b] = det;
        g_pot[b] = 0.0f;
    }

    float r0 = r[3*ga+0], r1 = r[3*ga+1], r2 = r[3*ga+2];
    float s0 = r0*i00 + r1*i10 + r2*i20;
    float s1 = r0*i01 + r1*i11 + r2*i21;
    float s2 = r0*i02 + r1*i12 + r2*i22;

    float fn = (float)n;
    float u, f, sx, cx, sy, cy, sz, cz;
    u = fn * s0; f = u - rintf(u); sincospi_fast(2.0f * f * 0.5f + f, &sx, &cx); // 2f in [-1,1]? no:
    // NOTE: f in [-0.5,0.5] -> angle = 2*pi*f. sincospi_fast takes x with sin(pi*x).
    // 2*pi*f = pi*(2f), and 2f in [-1,1]: out of poly range. Re-reduce: handled below.
    // (recomputed properly below; the line above is discarded)
    {
        float x = 2.0f * f;                 // in [-1, 1]
        // wrap to [-0.5, 0.5] with angle identity: sin(pi x) = sign flip trick
        float xr = x - rintf(x);            // in [-0.5, 0.5]
        float par = x - xr;                 // -1, 0, or +1
        sincospi_fast(xr, &sx, &cx);
        if (par != 0.0f) { sx = -sx; cx = -cx; }
    }
    u = fn * s1; f = u - rintf(u);
    {
        float x = 2.0f * f;
        float xr = x - rintf(x);
        float par = x - xr;
        sincospi_fast(xr, &sy, &cy);
        if (par != 0.0f) { sy = -sy; cy = -cy; }
    }
    u = fn * s2; f = u - rintf(u);
    {
        float x = 2.0f * f;
        float xr = x - rintf(x);
        float par = x - xr;
        sincospi_fast(xr, &sz, &cz);
        if (par != 0.0f) { sz = -sz; cz = -cz; }
    }

    float qv = q[ga];
    g_tabx[b][n][a] = make_float2(qv * cx, qv * sx);
    g_taby[b][n][a] = make_float2(cy, sy);
    if (n >= 1) g_tabz[b][n-1][a] = make_float2(cz, sz);
}

// ---------------- kernel 2 body: structure factors + fused reduction ----------
// Block = (b, n1, m2, S). S=0: n3 in [-5,5]; S=1: |n3| in [6,10].
template<int S>
__device__ __forceinline__ void k_main_body() {
    int blk = blockIdx.x;
    int b   = blk / 121;
    int rem = blk - b * 121;
    int n1  = rem / 11;
    int m2  = rem - n1 * 11;

    constexpr int  MLO  = S ? 6 : 1;
    constexpr bool HASC = (S == 0);
    constexpr int  ENT  = HASC ? 11 : 10;   // complex entries per n2-sign

    float g00 = TWOPI_F*g_cinv[b][0][0], g01 = TWOPI_F*g_cinv[b][1][0], g02 = TWOPI_F*g_cinv[b][2][0];
    float g10 = TWOPI_F*g_cinv[b][0][1], g11 = TWOPI_F*g_cinv[b][1][1], g12 = TWOPI_F*g_cinv[b][2][1];
    float g20 = TWOPI_F*g_cinv[b][0][2], g21 = TWOPI_F*g_cinv[b][1][2], g22 = TWOPI_F*g_cinv[b][2][2];

    // conservative per-block activity filter over this block's n3 set
    bool any = false;
    #pragma unroll
    for (int sg = 0; sg < 2; sg++) {
        float fn2 = sg ? -(float)m2 : (float)m2;
        #pragma unroll
        for (int j = 0; j < ENT; j++) {
            int n3i = S ? ((j < 5) ? (6 + j) : -(j + 1)) : (j - 5);
            float n3 = (float)n3i;
            float kv0 = n1*g00 + fn2*g01 + n3*g02;
            float kv1 = n1*g10 + fn2*g11 + n3*g12;
            float kv2 = n1*g20 + fn2*g21 + n3*g22;
            float ksq = kv0*kv0 + kv1*kv1 + kv2*kv2;
            any = any || (ksq > 0.0f && ksq <= KSQ_MAX_F * 1.001f);
        }
    }
    if (!any) return;

    const float2* __restrict__ tx = &g_tabx[b][n1][0];
    const float2* __restrict__ ty = &g_taby[b][m2][0];

    float cr0 = 0.f, ci0 = 0.f, cr1 = 0.f, ci1 = 0.f;   // center (S0 only)
    u64 P0[5], M0[5], P1[5], M1[5];   // M stored as (re, -im)
    #pragma unroll
    for (int m = 0; m < 5; m++) { P0[m]=0; M0[m]=0; P1[m]=0; M1[m]=0; }

    for (int a = threadIdx.x; a < NPER; a += NT) {
        float2 X = tx[a];
        float2 Y = ty[a];
        float p  = X.x*Y.x, qq = X.y*Y.y, rr = X.x*Y.y, ss = X.y*Y.x;
        float ar0 = p - qq, ar1 = p + qq;       // n2 = +m2 / -m2
        float ai0 = rr + ss, ai1 = ss - rr;
        if (HASC) { cr0 += ar0; ci0 += ai0; cr1 += ar1; ci1 += ai1; }
        u64 A0 = pk(ar0, ar0), I0 = pk(ai0, ai0), nI0 = pk(-ai0, -ai0);
        u64 A1 = pk(ar1, ar1), I1 = pk(ai1, ai1), nI1 = pk(-ai1, -ai1);
        #pragma unroll
        for (int m = 0; m < 5; m++) {
            // w1 = (Zx, Zy) loaded directly as a 64-bit pair (SoA, coalesced)
            u64 w1 = *(const u64*)&g_tabz[b][MLO - 1 + m][a];
            float2 Z = upk(w1);
            u64 w2 = pk(-Z.y, Z.x);
            // P(+n3): (re,im) += ar*w1 + ai*w2
            fma2(P0[m], A0, w1); fma2(P0[m], I0, w2);
            fma2(P1[m], A1, w1); fma2(P1[m], I1, w2);
            // M(-n3) stored (re,-im): += ar*w1 + (-ai)*w2
            fma2(M0[m], A0, w1); fma2(M0[m], nI0, w2);
            fma2(M1[m], A1, w1); fma2(M1[m], nI1, w2);
        }
    }

    // ---- pack entries, 3-level warp reduce -> 16 partials per entry ----
    // per-sign entry order: [center (S0)] [P m=MLO..MLO+4] [M m=MLO..MLO+4]
    __shared__ float red[16][2 * ENT * 2];
    __shared__ float cont[NT];
    u64 packed[2 * ENT];
    if (HASC) {
        packed[0]   = pk(cr0, ci0);
        packed[ENT] = pk(cr1, ci1);
    }
    constexpr int PB = HASC ? 1 : 0;
    #pragma unroll
    for (int m = 0; m < 5; m++) {
        packed[PB + m]           = P0[m];
        packed[PB + 5 + m]       = M0[m];
        packed[ENT + PB + m]     = P1[m];
        packed[ENT + PB + 5 + m] = M1[m];
    }
    int w = threadIdx.x >> 5, lane = threadIdx.x & 31;
    #pragma unroll
    for (int j = 0; j < 2 * ENT; j++) {
        u64 v = packed[j];
        v = add2(v, __shfl_xor_sync(0xffffffffu, v, 16));
        v = add2(v, __shfl_xor_sync(0xffffffffu, v, 8));
        v = add2(v, __shfl_xor_sync(0xffffffffu, v, 4));
        if (lane < 4) {
            float2 f2 = upk(v);
            red[w*4 + lane][2*j]   = f2.x;
            red[w*4 + lane][2*j+1] = f2.y;
        }
    }
    __syncthreads();

    // ---- per-kpoint weighting ----
    float c = 0.0f;
    int t = threadIdx.x;
    if (t < 2 * ENT) {
        int sgn = t / ENT, j = t - sgn * ENT;
        if (!(m2 == 0 && sgn == 1)) {            // n2 = -0 duplicates +0
            // entry j -> n3
            int n3i;
            bool isM;
            if (HASC) {
                if (j == 0)      { n3i = 0;            isM = false; }
                else if (j <= 5) { n3i = j;            isM = false; }   // P, m = j
                else             { n3i = -(j - 5);     isM = true;  }   // M, m = j-5
            } else {
                if (j < 5)       { n3i = 6 + j;        isM = false; }   // P, m = 6+j
                else             { n3i = -(6 + j - 5); isM = true;  }   // M
            }
            float Sr = 0.0f, Sv = 0.0f;
            int o = sgn * ENT + j;
            #pragma unroll
            for (int pI = 0; pI < 16; pI++) {
                Sr += red[pI][2*o];
                Sv += red[pI][2*o+1];
            }
            float Si = isM ? -Sv : Sv;           // M bank stored (re,-im)
            float fn2 = sgn ? -(float)m2 : (float)m2;
            float n3  = (float)n3i;
            float kv0 = n1*g00 + fn2*g01 + n3*g02;
            float kv1 = n1*g10 + fn2*g11 + n3*g12;
            float kv2 = n1*g20 + fn2*g21 + n3*g22;
            float ksq = kv0*kv0 + kv1*kv1 + kv2*kv2;
            if (ksq > 0.0f && ksq <= KSQ_MAX_F) {
                float wgt  = (n1 > 0) ? 2.0f : 1.0f;
                float kfac = expf(-0.5f * ksq) / (ksq + EPS_F);
                c = wgt * kfac * (Sr*Sr + Si*Si);
            }
        }
    }
    cont[t] = c;
    __syncthreads();
    #pragma unroll
    for (int s = NT/2; s > 0; s >>= 1) {
        if (t < s) cont[t] += cont[t + s];
        __syncthreads();
    }
    if (t == 0) atomicAdd(&g_pot[b], cont[0]);
}

__global__ void __launch_bounds__(NT) k_main() {
    if (blockIdx.y == 0) k_main_body<0>();
    else                 k_main_body<1>();
}

// ---------------- kernel 3: self energy + final output ----------------
__global__ void k_final(const float* __restrict__ q, float* __restrict__ out) {
    int b = blockIdx.x;
    __shared__ float sd[128];
    float s = 0.0f;
    for (int a = threadIdx.x; a < NPER; a += 128) {
        float qv = q[b * NPER + a];
        s += qv * qv;
    }
    sd[threadIdx.x] = s;
    __syncthreads();
    #pragma unroll
    for (int t = 64; t > 0; t >>= 1) {
        if (threadIdx.x < t) sd[threadIdx.x] += sd[threadIdx.x + t];
        __syncthreads();
    }
    if (threadIdx.x == 0) {
        float pot = g_pot[b] / g_vol[b] - sd[0] * INV_SELF;
        out[b] = pot * NORM_F;
    }
}

// ---------------- launch ----------------
extern "C" void kernel_launch(void* const* d_in, const int* in_sizes, int n_in,
                              void* d_out, int out_size) {
    const float* q    = (const float*)d_in[0];
    const float* r    = (const float*)d_in[1];
    const float* cell = (const float*)d_in[2];
    float* out = (float*)d_out;

    k_tab<<<(NN * NATOMS + 255) / 256, 256>>>(q, r, cell);
    k_main<<<dim3(BB * 121, 2), NT>>>();
    k_final<<<BB, 128>>>(q, out);
}

// round 7
// speedup vs baseline: 1.1000x; 1.0125x over previous
#include <cuda_runtime.h>
#include <math.h>

// Problem constants (static per the reference module)
#define BB      4
#define NPER    2000
#define NATOMS  (BB*NPER)
#define NN      11            // n = 0..10 per axis
#define NT      128           // threads per k_main block

#define KSQ_MAX_F   9.8696044010893586f   // fp32(pi^2), as JAX compares
#define TWOPI_F     6.2831854820251465f
#define INV_SELF    0.0634936359342410f   // 1/(sigma*(2*pi)^1.5)
#define NORM_F      90.0474f
#define EPS_F       1e-6f

typedef unsigned long long u64;

__device__ __forceinline__ u64 pk(float lo, float hi) {
    u64 r; asm("mov.b64 %0, {%1, %2};" : "=l"(r) : "f"(lo), "f"(hi)); return r;
}
__device__ __forceinline__ float2 upk(u64 v) {
    float lo, hi; asm("mov.b64 {%0, %1}, %2;" : "=f"(lo), "=f"(hi) : "l"(v));
    return make_float2(lo, hi);
}
__device__ __forceinline__ void fma2(u64& d, u64 a, u64 b) {
    asm("fma.rn.f32x2 %0, %1, %2, %0;" : "+l"(d) : "l"(a), "l"(b));
}
__device__ __forceinline__ u64 add2(u64 a, u64 b) {
    u64 d; asm("add.rn.f32x2 %0, %1, %2;" : "=l"(d) : "l"(a), "l"(b)); return d;
}

// fast sinpi/cospi on f in [-0.5, 0.5] (Taylor, max err ~3.6e-6 abs)
__device__ __forceinline__ void sincospi_fast(float f, float* s, float* c) {
    float t = f * f;
    float sp = fmaf(t, 0.0821458866f, -0.599264529f);
    sp = fmaf(t, sp, 2.55016404f);
    sp = fmaf(t, sp, -5.16771278f);
    sp = fmaf(t, sp, 3.14159265f);
    *s = f * sp;
    float cp = fmaf(t, -0.0258068917f, 0.235330631f);
    cp = fmaf(t, cp, -1.33526277f);
    cp = fmaf(t, cp, 4.05871213f);
    cp = fmaf(t, cp, -4.93480220f);
    *c = fmaf(t, cp, 1.0f);
}

// full-range: angle = 2*pi*f with f in [-0.5,0.5]
__device__ __forceinline__ void sc_2pi(float f, float* s, float* c) {
    float x = 2.0f * f;               // in [-1, 1]
    float xr = x - rintf(x);          // in [-0.5, 0.5]
    float par = x - xr;               // -1, 0, +1
    sincospi_fast(xr, s, c);
    if (par != 0.0f) { *s = -*s; *c = -*c; }
}

// ---------------- device scratch ----------------
__device__ float    g_cinv[BB][3][3];
__device__ float    g_vol[BB];
__device__ float    g_pot[BB];
__device__ unsigned g_cnt[BB];
__device__ float2   g_tabx[BB][NN][NPER];   // q * e^{i 2pi n s0}
__device__ float2   g_taby[BB][NN][NPER];   //     e^{i 2pi n s1}
__device__ float4   g_tabz[BB][NPER];       // {Ez1.re, Ez1.im, Ez6.re, Ez6.im}

// ---------------- kernel 1: phase tables, thread = (axis, atom) ----------------
__global__ void k_tab(const float* __restrict__ q, const float* __restrict__ r,
                      const float* __restrict__ cell) {
    int idx = blockIdx.x * blockDim.x + threadIdx.x;
    if (idx >= 3 * NATOMS) return;
    int axis = idx / NATOMS;
    int ga   = idx - axis * NATOMS;
    int b    = ga / NPER;
    int a    = ga - b * NPER;

    const float* m = cell + b * 9;
    float m00=m[0], m01=m[1], m02=m[2];
    float m10=m[3], m11=m[4], m12=m[5];
    float m20=m[6], m21=m[7], m22=m[8];
    float c00 = m11*m22 - m12*m21;
    float c01 = m12*m20 - m10*m22;
    float c02 = m10*m21 - m11*m20;
    float det = m00*c00 + m01*c01 + m02*c02;
    float inv = 1.0f / det;
    float i00 = c00 * inv;
    float i01 = (m02*m21 - m01*m22) * inv;
    float i02 = (m01*m12 - m02*m11) * inv;
    float i10 = c01 * inv;
    float i11 = (m00*m22 - m02*m20) * inv;
    float i12 = (m02*m10 - m00*m12) * inv;
    float i20 = c02 * inv;
    float i21 = (m01*m20 - m00*m21) * inv;
    float i22 = (m00*m11 - m01*m10) * inv;

    if (axis == 2 && a == 0) {
        g_cinv[b][0][0]=i00; g_cinv[b][0][1]=i01; g_cinv[b][0][2]=i02;
        g_cinv[b][1][0]=i10; g_cinv[b][1][1]=i11; g_cinv[b][1][2]=i12;
        g_cinv[b][2][0]=i20; g_cinv[b][2][1]=i21; g_cinv[b][2][2]=i22;
        g_vol[b] = det;
        g_pot[b] = 0.0f;
        g_cnt[b] = 0u;
    }

    float r0 = r[3*ga+0], r1 = r[3*ga+1], r2 = r[3*ga+2];

    if (axis == 0) {
        float s0 = r0*i00 + r1*i10 + r2*i20;
        float f = s0 - rintf(s0);
        float si, co; sc_2pi(f, &si, &co);
        float qv = q[ga];
        float Xr = qv, Xi = 0.0f;            // X_n = q * Ex^n
        #pragma unroll
        for (int n = 0; n < NN; n++) {
            g_tabx[b][n][a] = make_float2(Xr, Xi);
            float t = Xr*co - Xi*si; Xi = Xr*si + Xi*co; Xr = t;
        }
    } else if (axis == 1) {
        float s1 = r0*i01 + r1*i11 + r2*i21;
        float f = s1 - rintf(s1);
        float si, co; sc_2pi(f, &si, &co);
        float Yr = 1.0f, Yi = 0.0f;
        #pragma unroll
        for (int n = 0; n < NN; n++) {
            g_taby[b][n][a] = make_float2(Yr, Yi);
            float t = Yr*co - Yi*si; Yi = Yr*si + Yi*co; Yr = t;
        }
    } else {
        float s2 = r0*i02 + r1*i12 + r2*i22;
        float f = s2 - rintf(s2);
        float si, co; sc_2pi(f, &si, &co);
        // Ez1 = (co, si); Ez6 = Ez1^6 via squarings
        float e2r = co*co - si*si,  e2i = 2.0f*co*si;
        float e3r = e2r*co - e2i*si, e3i = e2r*si + e2i*co;
        float e6r = e3r*e3r - e3i*e3i, e6i = 2.0f*e3r*e3i;
        g_tabz[b][a] = make_float4(co, si, e6r, e6i);
    }
}

// ---------------- kernel 2: structure factors + weighting + fused final -------
// Block = (b, n1, m2). All n3 (via Ez recurrence), both n2 signs.
__global__ void __launch_bounds__(NT) k_main(const float* __restrict__ q,
                                             float* __restrict__ out) {
    int blk = blockIdx.x;
    int b   = blk / 121;
    int rem = blk - b * 121;
    int n1  = rem / 11;
    int m2  = rem - n1 * 11;
    int tid = threadIdx.x;

    float g00 = TWOPI_F*g_cinv[b][0][0], g01 = TWOPI_F*g_cinv[b][1][0], g02 = TWOPI_F*g_cinv[b][2][0];
    float g10 = TWOPI_F*g_cinv[b][0][1], g11 = TWOPI_F*g_cinv[b][1][1], g12 = TWOPI_F*g_cinv[b][2][1];
    float g20 = TWOPI_F*g_cinv[b][0][2], g21 = TWOPI_F*g_cinv[b][1][2], g22 = TWOPI_F*g_cinv[b][2][2];

    // parallel selection: mmax = max in-cutoff |n3| (with slack), -1 if none
    __shared__ int s_sel;
    __shared__ float red[16][84];
    __shared__ float cont[NT];
    if (tid == 0) s_sel = -1;
    __syncthreads();
    if (tid < 42) {
        int sg = tid / 21, j = tid - sg * 21;
        int n3i = j - 10;
        float fn2 = sg ? -(float)m2 : (float)m2;
        float n3 = (float)n3i;
        float kv0 = n1*g00 + fn2*g01 + n3*g02;
        float kv1 = n1*g10 + fn2*g11 + n3*g12;
        float kv2 = n1*g20 + fn2*g21 + n3*g22;
        float ksq = kv0*kv0 + kv1*kv1 + kv2*kv2;
        if (ksq > 0.0f && ksq <= KSQ_MAX_F * 1.001f)
            atomicMax(&s_sel, n3i < 0 ? -n3i : n3i);
    }
    __syncthreads();
    int  mmax   = s_sel;
    bool active = (mmax >= 0);

    if (active) {
        const float2* __restrict__ tx = &g_tabx[b][n1][0];
        const float2* __restrict__ ty = &g_taby[b][m2][0];
        const float4* __restrict__ tz = &g_tabz[b][0];

        u64 C0 = 0, C1 = 0;
        u64 P0[10], M0[10], P1[10], M1[10];   // M stored (re, -im)
        #pragma unroll
        for (int m = 0; m < 10; m++) { P0[m]=0; M0[m]=0; P1[m]=0; M1[m]=0; }

        for (int a = tid; a < NPER; a += NT) {
            float2 X = tx[a];
            float2 Y = ty[a];
            float4 ZS = tz[a];
            float p  = X.x*Y.x, qq = X.y*Y.y, rr = X.x*Y.y, ss = X.y*Y.x;
            float ar0 = p - qq, ar1 = p + qq;       // n2 = +m2 / -m2
            float ai0 = rr + ss, ai1 = ss - rr;
            u64 v1_0 = pk(ar0, ai0), v2_0 = pk(-ai0, ar0);
            u64 u1_0 = pk(ar0, -ai0), u2_0 = pk(ai0, ar0);
            u64 v1_1 = pk(ar1, ai1), v2_1 = pk(-ai1, ar1);
            u64 u1_1 = pk(ar1, -ai1), u2_1 = pk(ai1, ar1);
            C0 = add2(C0, v1_0);
            C1 = add2(C1, v1_1);
            float e1r = ZS.x, e1i = ZS.y;
            float Zr = e1r, Zi = e1i;
            #pragma unroll
            for (int m = 1; m <= 10; m++) {
                if (m > mmax) break;
                if (m == 6)      { Zr = ZS.z; Zi = ZS.w; }
                else if (m > 1)  { float t = Zr*e1r - Zi*e1i;
                                   Zi = Zr*e1i + Zi*e1r; Zr = t; }
                u64 Zx2 = pk(Zr, Zr), Zy2 = pk(Zi, Zi);
                // P(+n3): (re,im)   += Zx*(ar,ai)  + Zy*(-ai,ar)
                // M(-n3): (re,-im)  += Zx*(ar,-ai) + Zy*( ai,ar)
                fma2(P0[m-1], Zx2, v1_0); fma2(P0[m-1], Zy2, v2_0);
                fma2(M0[m-1], Zx2, u1_0); fma2(M0[m-1], Zy2, u2_0);
                fma2(P1[m-1], Zx2, v1_1); fma2(P1[m-1], Zy2, v2_1);
                fma2(M1[m-1], Zx2, u1_1); fma2(M1[m-1], Zy2, u2_1);
            }
        }

        // ---- pack to 42 entries, 3-level warp reduce -> 16 partials ----
        u64 packed[42];
        packed[0] = C0;
        packed[1] = C1;
        #pragma unroll
        for (int m = 0; m < 10; m++) {
            packed[2 + m]  = P0[m];
            packed[12 + m] = M0[m];
            packed[22 + m] = P1[m];
            packed[32 + m] = M1[m];
        }
        int w = tid >> 5, lane = tid & 31;
        #pragma unroll
        for (int j = 0; j < 42; j++) {
            u64 v = packed[j];
            v = add2(v, __shfl_xor_sync(0xffffffffu, v, 16));
            v = add2(v, __shfl_xor_sync(0xffffffffu, v, 8));
            v = add2(v, __shfl_xor_sync(0xffffffffu, v, 4));
            if (lane < 4) {
                float2 f2 = upk(v);
                red[w*4 + lane][2*j]   = f2.x;
                red[w*4 + lane][2*j+1] = f2.y;
            }
        }
        __syncthreads();

        // ---- per-kpoint weighting (verbatim mask math) ----
        float c = 0.0f;
        if (tid < 42) {
            int sgn = tid / 21, j = tid - sgn * 21;   // j = n3 index 0..20
            if (!(m2 == 0 && sgn == 1)) {             // n2 = -0 duplicates +0
                int o;
                if (j == 10)      o = sgn;                       // center
                else if (j > 10)  o = 2  + sgn*20 + (j - 11);    // P bank, m = j-10
                else              o = 12 + sgn*20 + (9 - j);     // M bank, m = 10-j
                float Sr = 0.0f, Sv = 0.0f;
                #pragma unroll
                for (int pI = 0; pI < 16; pI++) {
                    Sr += red[pI][2*o];
                    Sv += red[pI][2*o+1];
                }
                float Si = (j < 10) ? -Sv : Sv;       // M bank stored (re,-im)
                float fn2 = sgn ? -(float)m2 : (float)m2;
                float n3  = (float)(j - 10);
                float kv0 = n1*g00 + fn2*g01 + n3*g02;
                float kv1 = n1*g10 + fn2*g11 + n3*g12;
                float kv2 = n1*g20 + fn2*g21 + n3*g22;
                float ksq = kv0*kv0 + kv1*kv1 + kv2*kv2;
                if (ksq > 0.0f && ksq <= KSQ_MAX_F) {
                    float wgt  = (n1 > 0) ? 2.0f : 1.0f;
                    float kfac = expf(-0.5f * ksq) / (ksq + EPS_F);
                    c = wgt * kfac * (Sr*Sr + Si*Si);
                }
            }
        }
        cont[tid] = c;
        __syncthreads();
        #pragma unroll
        for (int s = NT/2; s > 0; s >>= 1) {
            if (tid < s) cont[tid] += cont[tid + s];
            __syncthreads();
        }
        if (tid == 0) atomicAdd(&g_pot[b], cont[0]);
        __syncthreads();
    }

    // ---- fused finalization: last block of this batch writes out[b] ----
    __shared__ bool s_last;
    if (tid == 0) {
        __threadfence();
        unsigned old = atomicAdd(&g_cnt[b], 1u);
        s_last = (old == 120u);
    }
    __syncthreads();
    if (s_last) {
        float s = 0.0f;
        for (int a = tid; a < NPER; a += NT) {
            float qv = q[b * NPER + a];
            s += qv * qv;
        }
        cont[tid] = s;
        __syncthreads();
        #pragma unroll
        for (int t2 = NT/2; t2 > 0; t2 >>= 1) {
            if (tid < t2) cont[tid] += cont[tid + t2];
            __syncthreads();
        }
        if (tid == 0) {
            float potv = atomicAdd(&g_pot[b], 0.0f);   // coherent read
            float pot = potv / g_vol[b] - cont[0] * INV_SELF;
            out[b] = pot * NORM_F;
        }
    }
}

// ---------------- launch ----------------
extern "C" void kernel_launch(void* const* d_in, const int* in_sizes, int n_in,
                              void* d_out, int out_size) {
    const float* q    = (const float*)d_in[0];
    const float* r    = (const float*)d_in[1];
    const float* cell = (const float*)d_in[2];
    float* out = (float*)d_out;

    k_tab<<<(3 * NATOMS + 255) / 256, 256>>>(q, r, cell);
    k_main<<<BB * 121, NT>>>(q, out);
}

// round 8
// speedup vs baseline: 1.2092x; 1.0992x over previous
#include <cuda_runtime.h>
#include <math.h>

// Problem constants (static per the reference module)
#define BB      4
#define NPER    2000
#define NATOMS  (BB*NPER)
#define NN      11            // n = 0..10 per axis
#define NT      128           // threads per k_main block

#define KSQ_MAX_F   9.8696044010893586f   // fp32(pi^2), as JAX compares
#define TWOPI_F     6.2831854820251465f
#define INV_SELF    0.0634936359342410f   // 1/(sigma*(2*pi)^1.5)
#define NORM_F      90.0474f
#define EPS_F       1e-6f

typedef unsigned long long u64;

__device__ __forceinline__ u64 pk(float lo, float hi) {
    u64 r; asm("mov.b64 %0, {%1, %2};" : "=l"(r) : "f"(lo), "f"(hi)); return r;
}
__device__ __forceinline__ float2 upk(u64 v) {
    float lo, hi; asm("mov.b64 {%0, %1}, %2;" : "=f"(lo), "=f"(hi) : "l"(v));
    return make_float2(lo, hi);
}
__device__ __forceinline__ void fma2(u64& d, u64 a, u64 b) {
    asm("fma.rn.f32x2 %0, %1, %2, %0;" : "+l"(d) : "l"(a), "l"(b));
}
__device__ __forceinline__ u64 add2(u64 a, u64 b) {
    u64 d; asm("add.rn.f32x2 %0, %1, %2;" : "=l"(d) : "l"(a), "l"(b)); return d;
}
__device__ __forceinline__ u64 mul2(u64 a, u64 b) {
    u64 d; asm("mul.rn.f32x2 %0, %1, %2;" : "=l"(d) : "l"(a), "l"(b)); return d;
}

// fast sinpi/cospi on f in [-0.5, 0.5] (Taylor, max err ~3.6e-6 abs)
__device__ __forceinline__ void sincospi_fast(float f, float* s, float* c) {
    float t = f * f;
    float sp = fmaf(t, 0.0821458866f, -0.599264529f);
    sp = fmaf(t, sp, 2.55016404f);
    sp = fmaf(t, sp, -5.16771278f);
    sp = fmaf(t, sp, 3.14159265f);
    *s = f * sp;
    float cp = fmaf(t, -0.0258068917f, 0.235330631f);
    cp = fmaf(t, cp, -1.33526277f);
    cp = fmaf(t, cp, 4.05871213f);
    cp = fmaf(t, cp, -4.93480220f);
    *c = fmaf(t, cp, 1.0f);
}

// full-range: angle = 2*pi*f with f in [-0.5,0.5]
__device__ __forceinline__ void sc_2pi(float f, float* s, float* c) {
    float x = 2.0f * f;               // in [-1, 1]
    float xr = x - rintf(x);          // in [-0.5, 0.5]
    float par = x - xr;               // -1, 0, +1
    sincospi_fast(xr, s, c);
    if (par != 0.0f) { *s = -*s; *c = -*c; }
}

// ---------------- device scratch ----------------
__device__ float    g_cinv[BB][3][3];
__device__ float    g_vol[BB];
__device__ float    g_pot[BB];
__device__ unsigned g_cnt[BB];
__device__ float2   g_tabx[BB][NN][NPER];   // q * e^{i 2pi n s0}
__device__ float2   g_taby[BB][NN][NPER];   //     e^{i 2pi n s1}
__device__ float2   g_tabz[BB][NPER];       // Ez1 = e^{i 2pi s2}

// ---------------- kernel 1: phase tables, grid (atoms, 12) ----------------
// blockIdx.y in 0..10: writes tabx/taby for n = blockIdx.y
// blockIdx.y == 11:    writes z seed + cell-derived constants
__global__ void k_tab(const float* __restrict__ q, const float* __restrict__ r,
                      const float* __restrict__ cell) {
    int gy = blockIdx.y;
    int ga = blockIdx.x * blockDim.x + threadIdx.x;
    if (ga >= NATOMS) return;
    int b = ga / NPER;
    int a = ga - b * NPER;

    const float* m = cell + b * 9;
    float m00=m[0], m01=m[1], m02=m[2];
    float m10=m[3], m11=m[4], m12=m[5];
    float m20=m[6], m21=m[7], m22=m[8];
    float c00 = m11*m22 - m12*m21;
    float c01 = m12*m20 - m10*m22;
    float c02 = m10*m21 - m11*m20;
    float det = m00*c00 + m01*c01 + m02*c02;
    float inv = 1.0f / det;
    float i00 = c00 * inv;
    float i01 = (m02*m21 - m01*m22) * inv;
    float i02 = (m01*m12 - m02*m11) * inv;
    float i10 = c01 * inv;
    float i11 = (m00*m22 - m02*m20) * inv;
    float i12 = (m02*m10 - m00*m12) * inv;
    float i20 = c02 * inv;
    float i21 = (m01*m20 - m00*m21) * inv;
    float i22 = (m00*m11 - m01*m10) * inv;

    float r0 = r[3*ga+0], r1 = r[3*ga+1], r2 = r[3*ga+2];

    if (gy == 11) {
        if (a == 0) {
            g_cinv[b][0][0]=i00; g_cinv[b][0][1]=i01; g_cinv[b][0][2]=i02;
            g_cinv[b][1][0]=i10; g_cinv[b][1][1]=i11; g_cinv[b][1][2]=i12;
            g_cinv[b][2][0]=i20; g_cinv[b][2][1]=i21; g_cinv[b][2][2]=i22;
            g_vol[b] = det;
            g_pot[b] = 0.0f;
            g_cnt[b] = 0u;
        }
        float s2 = r0*i02 + r1*i12 + r2*i22;
        float f = s2 - rintf(s2);
        float si, co; sc_2pi(f, &si, &co);
        g_tabz[b][a] = make_float2(co, si);
    } else {
        int n = gy;
        float fn = (float)n;
        float s0 = r0*i00 + r1*i10 + r2*i20;
        float s1 = r0*i01 + r1*i11 + r2*i21;
        float u, f, sx, cx, sy, cy;
        u = fn * s0; f = u - rintf(u); sc_2pi(f, &sx, &cx);
        u = fn * s1; f = u - rintf(u); sc_2pi(f, &sy, &cy);
        float qv = q[ga];
        g_tabx[b][n][a] = make_float2(qv * cx, qv * sx);
        g_taby[b][n][a] = make_float2(cy, sy);
    }
}

// ---------------- kernel 2: structure factors + weighting + fused final -------
// Block = (b, n1, m2). All n3 via packed Ez recurrence; both n2 signs.
// U/V trick: S(+m) = U + iV, S(-m) = U - iV with U = sum a*Zx, V = sum a*Zy.
__global__ void __launch_bounds__(NT) k_main(const float* __restrict__ q,
                                             float* __restrict__ out) {
    int blk = blockIdx.x;
    int b   = blk / 121;
    int rem = blk - b * 121;
    int n1  = rem / 11;
    int m2  = rem - n1 * 11;
    int tid = threadIdx.x;

    float g00 = TWOPI_F*g_cinv[b][0][0], g01 = TWOPI_F*g_cinv[b][1][0], g02 = TWOPI_F*g_cinv[b][2][0];
    float g10 = TWOPI_F*g_cinv[b][0][1], g11 = TWOPI_F*g_cinv[b][1][1], g12 = TWOPI_F*g_cinv[b][2][1];
    float g20 = TWOPI_F*g_cinv[b][0][2], g21 = TWOPI_F*g_cinv[b][1][2], g22 = TWOPI_F*g_cinv[b][2][2];

    // parallel selection: mmax = max in-cutoff |n3| (with slack), -1 if none
    __shared__ int s_sel;
    __shared__ float red[16][84];
    __shared__ float cont[NT];
    if (tid == 0) s_sel = -1;
    __syncthreads();
    if (tid < 42) {
        int sg = tid / 21, j = tid - sg * 21;
        int n3i = j - 10;
        float fn2 = sg ? -(float)m2 : (float)m2;
        float n3 = (float)n3i;
        float kv0 = n1*g00 + fn2*g01 + n3*g02;
        float kv1 = n1*g10 + fn2*g11 + n3*g12;
        float kv2 = n1*g20 + fn2*g21 + n3*g22;
        float ksq = kv0*kv0 + kv1*kv1 + kv2*kv2;
        if (ksq > 0.0f && ksq <= KSQ_MAX_F * 1.001f)
            atomicMax(&s_sel, n3i < 0 ? -n3i : n3i);
    }
    __syncthreads();
    int  mmax   = s_sel;
    bool active = (mmax >= 0);

    if (active) {
        const float2* __restrict__ tx = &g_tabx[b][n1][0];
        const float2* __restrict__ ty = &g_taby[b][m2][0];
        const float2* __restrict__ tz = &g_tabz[b][0];

        u64 C0 = 0, C1 = 0;
        u64 U0[10], V0[10], U1[10], V1[10];
        #pragma unroll
        for (int m = 0; m < 10; m++) { U0[m]=0; V0[m]=0; U1[m]=0; V1[m]=0; }

        // software-pipelined atom loop: prefetch next iteration's loads
        int a = tid;
        float2 X = tx[a];
        float2 Y = ty[a];
        float2 Z = tz[a];
        while (a < NPER) {
            int an = a + NT;
            int ap = (an < NPER) ? an : a;      // safe address
            float2 Xn = tx[ap];
            float2 Yn = ty[ap];
            float2 Zn = tz[ap];

            float p  = X.x*Y.x, qq = X.y*Y.y, rr = X.x*Y.y, ss = X.y*Y.x;
            float ar0 = p - qq, ar1 = p + qq;   // n2 = +m2 / -m2
            float ai0 = rr + ss, ai1 = ss - rr;
            u64 a0 = pk(ar0, ai0), a1 = pk(ar1, ai1);
            C0 = add2(C0, a0);
            C1 = add2(C1, a1);

            u64 E1R = pk(Z.x, Z.x), E1I = pk(Z.y, Z.y), nE1I = pk(-Z.y, -Z.y);
            u64 ZR = E1R, ZI = E1I;             // Ez^1 splats
            #pragma unroll
            for (int m = 1; m <= 10; m++) {
                if (m > mmax) break;
                if (m > 1) {
                    u64 t1 = mul2(ZI, nE1I); fma2(t1, ZR, E1R);   // new ZR
                    u64 t2 = mul2(ZI, E1R);  fma2(t2, ZR, E1I);   // new ZI
                    ZR = t1; ZI = t2;
                }
                fma2(U0[m-1], ZR, a0); fma2(V0[m-1], ZI, a0);
                fma2(U1[m-1], ZR, a1); fma2(V1[m-1], ZI, a1);
            }
            X = Xn; Y = Yn; Z = Zn; a = an;
        }

        // ---- pack to 42 entries, 3-level warp reduce -> 16 partials ----
        // layout: [0]=C0, [1]=C1, sign s: 2 + s*20 + 2(m-1) = U, +1 = V
        u64 packed[42];
        packed[0] = C0;
        packed[1] = C1;
        #pragma unroll
        for (int m = 0; m < 10; m++) {
            packed[2 + 2*m]      = U0[m];
            packed[3 + 2*m]      = V0[m];
            packed[22 + 2*m]     = U1[m];
            packed[23 + 2*m]     = V1[m];
        }
        int w = tid >> 5, lane = tid & 31;
        #pragma unroll
        for (int j = 0; j < 42; j++) {
            u64 v = packed[j];
            v = add2(v, __shfl_xor_sync(0xffffffffu, v, 16));
            v = add2(v, __shfl_xor_sync(0xffffffffu, v, 8));
            v = add2(v, __shfl_xor_sync(0xffffffffu, v, 4));
            if (lane < 4) {
                float2 f2 = upk(v);
                red[w*4 + lane][2*j]   = f2.x;
                red[w*4 + lane][2*j+1] = f2.y;
            }
        }
        __syncthreads();

        // ---- per-kpoint weighting (verbatim mask math) ----
        float c = 0.0f;
        if (tid < 42) {
            int sgn = tid / 21, j = tid - sgn * 21;   // j = n3 index 0..20
            if (!(m2 == 0 && sgn == 1)) {             // n2 = -0 duplicates +0
                float Sr, Si;
                if (j == 10) {
                    int o = sgn;
                    float cr = 0.0f, ci = 0.0f;
                    #pragma unroll
                    for (int pI = 0; pI < 16; pI++) {
                        cr += red[pI][2*o];
                        ci += red[pI][2*o+1];
                    }
                    Sr = cr; Si = ci;
                } else {
                    int mm = (j > 10) ? (j - 10) : (10 - j);
                    int ob = 2 + sgn*20 + 2*(mm - 1);     // U entry
                    float Ur = 0.0f, Ui = 0.0f, Vr = 0.0f, Vi = 0.0f;
                    #pragma unroll
                    for (int pI = 0; pI < 16; pI++) {
                        Ur += red[pI][2*ob];
                        Ui += red[pI][2*ob+1];
                        Vr += red[pI][2*ob+2];
                        Vi += red[pI][2*ob+3];
                    }
                    if (j > 10) { Sr = Ur - Vi; Si = Ui + Vr; }   // S(+m) = U + iV
                    else        { Sr = Ur + Vi; Si = Ui - Vr; }   // S(-m) = U - iV
                }
                float fn2 = sgn ? -(float)m2 : (float)m2;
                float n3  = (float)(j - 10);
                float kv0 = n1*g00 + fn2*g01 + n3*g02;
                float kv1 = n1*g10 + fn2*g11 + n3*g12;
                float kv2 = n1*g20 + fn2*g21 + n3*g22;
                float ksq = kv0*kv0 + kv1*kv1 + kv2*kv2;
                if (ksq > 0.0f && ksq <= KSQ_MAX_F) {
                    float wgt  = (n1 > 0) ? 2.0f : 1.0f;
                    float kfac = expf(-0.5f * ksq) / (ksq + EPS_F);
                    c = wgt * kfac * (Sr*Sr + Si*Si);
                }
            }
        }
        cont[tid] = c;
        __syncthreads();
        #pragma unroll
        for (int s = NT/2; s > 0; s >>= 1) {
            if (tid < s) cont[tid] += cont[tid + s];
            __syncthreads();
        }
        if (tid == 0) atomicAdd(&g_pot[b], cont[0]);
        __syncthreads();
    }

    // ---- fused finalization: last block of this batch writes out[b] ----
    __shared__ bool s_last;
    if (tid == 0) {
        __threadfence();
        unsigned old = atomicAdd(&g_cnt[b], 1u);
        s_last = (old == 120u);
    }
    __syncthreads();
    if (s_last) {
        float s = 0.0f;
        for (int a = tid; a < NPER; a += NT) {
            float qv = q[b * NPER + a];
            s += qv * qv;
        }
        cont[tid] = s;
        __syncthreads();
        #pragma unroll
        for (int t2 = NT/2; t2 > 0; t2 >>= 1) {
            if (tid < t2) cont[tid] += cont[tid + t2];
            __syncthreads();
        }
        if (tid == 0) {
            float potv = atomicAdd(&g_pot[b], 0.0f);   // coherent read
            float pot = potv / g_vol[b] - cont[0] * INV_SELF;
            out[b] = pot * NORM_F;
        }
    }
}

// ---------------- launch ----------------
extern "C" void kernel_launch(void* const* d_in, const int* in_sizes, int n_in,
                              void* d_out, int out_size) {
    const float* q    = (const float*)d_in[0];
    const float* r    = (const float*)d_in[1];
    const float* cell = (const float*)d_in[2];
    float* out = (float*)d_out;

    dim3 tgrid((NATOMS + 255) / 256, 12);
    k_tab<<<tgrid, 256>>>(q, r, cell);
    k_main<<<BB * 121, NT>>>(q, out);
}